// round 1
// baseline (speedup 1.0000x reference)
#include <cuda_runtime.h>

// QINCo: D=128, M=8, K=256, L=2, H=256, BS=1024
#define Dq   128
#define Mq   8
#define Kq   256
#define Hq   256
#define BSq  1024
#define NROW (BSq * Kq)          // 262144 candidate rows per step

// Output layout (float32): xhat[BS*D], codes[BS*M] (as float), side[0..7][BS*D]
#define OUT_CODES (BSq * Dq)                 // 131072
#define OUT_SIDE  (OUT_CODES + BSq * Mq)     // 139264

// ---------------- device scratch (static, no allocs) ----------------
__device__ float g_xhat[BSq * Dq];
__device__ float g_Ck[Kq * Dq];              // cb + cb@Wz^T
__device__ float g_A0[Kq * Hq];              // Ck@W1_0^T
__device__ float g_Xb[BSq * Dq];             // xhat@Wx^T + bc
__device__ float g_B0[BSq * Hq];             // Xb@W1_0^T
__device__ float g_Z1[NROW * Dq];            // 134 MB
__device__ float g_H1[NROW * Hq];            // 268 MB (relu'd hidden of layer 1)
__device__ float g_ZF[NROW * Dq];            // 134 MB (final candidate targets)
__device__ float g_dist[NROW];

// ---------------- step 0: code0 = argmin ||x - cb0_k||^2 ----------------
__global__ void k_code0(const float* __restrict__ x,
                        const float* __restrict__ cb0,
                        float* __restrict__ out) {
    __shared__ float s_x[Dq];
    __shared__ float s_v[256];
    __shared__ int   s_i[256];
    int b = blockIdx.x, t = threadIdx.x;
    if (t < Dq) s_x[t] = x[b * Dq + t];
    __syncthreads();
    const float* c = cb0 + t * Dq;
    float acc1 = 0.f, acc2 = 0.f;
    #pragma unroll 8
    for (int d = 0; d < Dq; d++) {
        float cv = c[d];
        acc1 = fmaf(cv, cv, acc1);
        acc2 = fmaf(s_x[d], cv, acc2);
    }
    s_v[t] = acc1 - 2.f * acc2;   // xn dropped: argmin-invariant
    s_i[t] = t;
    __syncthreads();
    for (int s = 128; s > 0; s >>= 1) {
        if (t < s) {
            float v2 = s_v[t + s]; int i2 = s_i[t + s];
            if (v2 < s_v[t] || (v2 == s_v[t] && i2 < s_i[t])) { s_v[t] = v2; s_i[t] = i2; }
        }
        __syncthreads();
    }
    int idx = s_i[0];
    if (t < Dq) {
        float v = cb0[idx * Dq + t];
        g_xhat[b * Dq + t] = v;
        out[OUT_SIDE + b * Dq + t] = v;   // side[0]
    }
    if (t == 0) out[OUT_CODES + b * Mq + 0] = (float)idx;
}

// ---------------- per-step small prep kernels ----------------
// Ck[k][d] = cb[k][d] + sum_d' cb[k][d'] * Wc[d][d']   (Wz = Wc[:, :D])
__global__ void k_ck(const float* __restrict__ cb, const float* __restrict__ Wcm) {
    __shared__ float s[Dq];
    int k = blockIdx.x, t = threadIdx.x;
    s[t] = cb[k * Dq + t];
    __syncthreads();
    float acc = s[t];
    const float* w = Wcm + t * (2 * Dq);
    #pragma unroll 8
    for (int d = 0; d < Dq; d++) acc = fmaf(s[d], w[d], acc);
    g_Ck[k * Dq + t] = acc;
}

// A0[k][h] = sum_d Ck[k][d] * W1_0[h][d]
__global__ void k_a0(const float* __restrict__ W10) {
    __shared__ float s[Dq];
    int k = blockIdx.x, t = threadIdx.x;
    if (t < Dq) s[t] = g_Ck[k * Dq + t];
    __syncthreads();
    float acc = 0.f;
    const float* w = W10 + t * Dq;
    #pragma unroll 8
    for (int d = 0; d < Dq; d++) acc = fmaf(s[d], w[d], acc);
    g_A0[k * Hq + t] = acc;
}

// Xb[b][j] = bc[j] + sum_d xhat[b][d] * Wc[j][D + d]
__global__ void k_xb(const float* __restrict__ Wcm, const float* __restrict__ bcm) {
    __shared__ float s[Dq];
    int b = blockIdx.x, t = threadIdx.x;
    s[t] = g_xhat[b * Dq + t];
    __syncthreads();
    float acc = bcm[t];
    const float* w = Wcm + t * (2 * Dq) + Dq;
    #pragma unroll 8
    for (int d = 0; d < Dq; d++) acc = fmaf(s[d], w[d], acc);
    g_Xb[b * Dq + t] = acc;
}

// B0[b][h] = sum_j Xb[b][j] * W1_0[h][j]
__global__ void k_b0(const float* __restrict__ W10) {
    __shared__ float s[Dq];
    int b = blockIdx.x, t = threadIdx.x;
    if (t < Dq) s[t] = g_Xb[b * Dq + t];
    __syncthreads();
    float acc = 0.f;
    const float* w = W10 + t * Dq;
    #pragma unroll 8
    for (int d = 0; d < Dq; d++) acc = fmaf(s[d], w[d], acc);
    g_B0[b * Hq + t] = acc;
}

// ---------------- GEMM A: Z1 = Ck+Xb + relu(A0+B0) @ W2_0^T ----------------
// tile 128 rows (one b, 128 k's) x 128 cols, contraction H=256 in chunks of 16
__global__ __launch_bounds__(256) void gemmA(const float* __restrict__ W20) {
    __shared__ __align__(16) float Rs[16][132];
    __shared__ __align__(16) float Ws[16][132];
    int bx = blockIdx.x;              // 0..2047
    int b  = bx >> 1;
    int k0 = (bx & 1) * 128;
    int row0 = b * Kq + k0;
    int tid = threadIdx.x;
    int tx = tid & 15, ty = tid >> 4;
    float acc[8][8] = {};
    const float* A0p = g_A0 + k0 * Hq;
    const float* B0p = g_B0 + b * Hq;
    for (int kk = 0; kk < Hq; kk += 16) {
        #pragma unroll
        for (int it = 0; it < 8; it++) {
            int idx = tid + it * 256;
            int r = idx >> 4, h = idx & 15;
            float v = A0p[r * Hq + kk + h] + B0p[kk + h];
            Rs[h][r] = fmaxf(v, 0.f);
        }
        #pragma unroll
        for (int it = 0; it < 8; it++) {
            int idx = tid + it * 256;
            int d = idx >> 4, h = idx & 15;
            Ws[h][d] = W20[d * Hq + kk + h];
        }
        __syncthreads();
        #pragma unroll
        for (int h = 0; h < 16; h++) {
            float4 a0 = *(const float4*)(&Rs[h][ty * 8]);
            float4 a1 = *(const float4*)(&Rs[h][ty * 8 + 4]);
            float4 w0 = *(const float4*)(&Ws[h][tx * 8]);
            float4 w1 = *(const float4*)(&Ws[h][tx * 8 + 4]);
            float a[8] = {a0.x,a0.y,a0.z,a0.w,a1.x,a1.y,a1.z,a1.w};
            float w[8] = {w0.x,w0.y,w0.z,w0.w,w1.x,w1.y,w1.z,w1.w};
            #pragma unroll
            for (int i = 0; i < 8; i++)
                #pragma unroll
                for (int j = 0; j < 8; j++)
                    acc[i][j] = fmaf(a[i], w[j], acc[i][j]);
        }
        __syncthreads();
    }
    const float* Ckp = g_Ck + k0 * Dq;
    const float* Xbp = g_Xb + b * Dq;
    #pragma unroll
    for (int i = 0; i < 8; i++) {
        int r = ty * 8 + i;
        int base = (row0 + r) * Dq + tx * 8;
        const float* ck = Ckp + r * Dq + tx * 8;
        const float* xb = Xbp + tx * 8;
        float4 o0 = make_float4(acc[i][0] + ck[0] + xb[0], acc[i][1] + ck[1] + xb[1],
                                acc[i][2] + ck[2] + xb[2], acc[i][3] + ck[3] + xb[3]);
        float4 o1 = make_float4(acc[i][4] + ck[4] + xb[4], acc[i][5] + ck[5] + xb[5],
                                acc[i][6] + ck[6] + xb[6], acc[i][7] + ck[7] + xb[7]);
        *(float4*)(&g_Z1[base])     = o0;
        *(float4*)(&g_Z1[base + 4]) = o1;
    }
}

// ---------------- GEMM B: H1 = relu(Z1 @ W1_1^T) ----------------
// tile 128 rows x 128 h-cols, contraction D=128 in chunks of 16; grid 4096
__global__ __launch_bounds__(256) void gemmB(const float* __restrict__ W11) {
    __shared__ __align__(16) float Zs[16][132];
    __shared__ __align__(16) float W1s[16][132];
    int bx = blockIdx.x;
    int row0 = (bx >> 1) * 128;
    int h0   = (bx & 1) * 128;
    int tid = threadIdx.x;
    int tx = tid & 15, ty = tid >> 4;
    float acc[8][8] = {};
    for (int dd = 0; dd < Dq; dd += 16) {
        #pragma unroll
        for (int it = 0; it < 8; it++) {
            int idx = tid + it * 256;
            int r = idx >> 4, d = idx & 15;
            Zs[d][r] = g_Z1[(row0 + r) * Dq + dd + d];
        }
        #pragma unroll
        for (int it = 0; it < 8; it++) {
            int idx = tid + it * 256;
            int c = idx >> 4, d = idx & 15;
            W1s[d][c] = W11[(h0 + c) * Dq + dd + d];
        }
        __syncthreads();
        #pragma unroll
        for (int d = 0; d < 16; d++) {
            float4 a0 = *(const float4*)(&Zs[d][ty * 8]);
            float4 a1 = *(const float4*)(&Zs[d][ty * 8 + 4]);
            float4 w0 = *(const float4*)(&W1s[d][tx * 8]);
            float4 w1 = *(const float4*)(&W1s[d][tx * 8 + 4]);
            float a[8] = {a0.x,a0.y,a0.z,a0.w,a1.x,a1.y,a1.z,a1.w};
            float w[8] = {w0.x,w0.y,w0.z,w0.w,w1.x,w1.y,w1.z,w1.w};
            #pragma unroll
            for (int i = 0; i < 8; i++)
                #pragma unroll
                for (int j = 0; j < 8; j++)
                    acc[i][j] = fmaf(a[i], w[j], acc[i][j]);
        }
        __syncthreads();
    }
    #pragma unroll
    for (int i = 0; i < 8; i++) {
        int r = ty * 8 + i;
        int base = (row0 + r) * Hq + h0 + tx * 8;
        float4 o0 = make_float4(fmaxf(acc[i][0], 0.f), fmaxf(acc[i][1], 0.f),
                                fmaxf(acc[i][2], 0.f), fmaxf(acc[i][3], 0.f));
        float4 o1 = make_float4(fmaxf(acc[i][4], 0.f), fmaxf(acc[i][5], 0.f),
                                fmaxf(acc[i][6], 0.f), fmaxf(acc[i][7], 0.f));
        *(float4*)(&g_H1[base])     = o0;
        *(float4*)(&g_H1[base + 4]) = o1;
    }
}

// ---------------- GEMM C: ZF = Z1 + H1 @ W2_1^T + xhat; dist epilogue ----------------
__global__ __launch_bounds__(256) void gemmC(const float* __restrict__ x,
                                             const float* __restrict__ W21) {
    __shared__ __align__(16) float Hs[16][132];
    __shared__ __align__(16) float Ws[16][132];
    __shared__ float s_ssq[128][17];
    __shared__ float s_sxz[128][17];
    __shared__ float s_x[Dq];
    __shared__ float s_xh[Dq];
    int bx = blockIdx.x;              // 0..2047
    int row0 = bx * 128;
    int b = bx >> 1;
    int tid = threadIdx.x;
    int tx = tid & 15, ty = tid >> 4;
    if (tid < Dq) { s_x[tid] = x[b * Dq + tid]; s_xh[tid] = g_xhat[b * Dq + tid]; }
    float acc[8][8] = {};
    for (int kk = 0; kk < Hq; kk += 16) {
        #pragma unroll
        for (int it = 0; it < 8; it++) {
            int idx = tid + it * 256;
            int r = idx >> 4, h = idx & 15;
            Hs[h][r] = g_H1[(row0 + r) * Hq + kk + h];
        }
        #pragma unroll
        for (int it = 0; it < 8; it++) {
            int idx = tid + it * 256;
            int d = idx >> 4, h = idx & 15;
            Ws[h][d] = W21[d * Hq + kk + h];
        }
        __syncthreads();
        #pragma unroll
        for (int h = 0; h < 16; h++) {
            float4 a0 = *(const float4*)(&Hs[h][ty * 8]);
            float4 a1 = *(const float4*)(&Hs[h][ty * 8 + 4]);
            float4 w0 = *(const float4*)(&Ws[h][tx * 8]);
            float4 w1 = *(const float4*)(&Ws[h][tx * 8 + 4]);
            float a[8] = {a0.x,a0.y,a0.z,a0.w,a1.x,a1.y,a1.z,a1.w};
            float w[8] = {w0.x,w0.y,w0.z,w0.w,w1.x,w1.y,w1.z,w1.w};
            #pragma unroll
            for (int i = 0; i < 8; i++)
                #pragma unroll
                for (int j = 0; j < 8; j++)
                    acc[i][j] = fmaf(a[i], w[j], acc[i][j]);
        }
        __syncthreads();
    }
    // epilogue: zf = acc + Z1 + xhat; store; per-row dist partials
    #pragma unroll
    for (int i = 0; i < 8; i++) {
        int r = ty * 8 + i;
        int base = (row0 + r) * Dq + tx * 8;
        float ssq = 0.f, sxz = 0.f;
        float zf[8];
        #pragma unroll
        for (int j = 0; j < 8; j++) {
            float v = acc[i][j] + g_Z1[base + j] + s_xh[tx * 8 + j];
            zf[j] = v;
            ssq = fmaf(v, v, ssq);
            sxz = fmaf(s_x[tx * 8 + j], v, sxz);
        }
        *(float4*)(&g_ZF[base])     = make_float4(zf[0], zf[1], zf[2], zf[3]);
        *(float4*)(&g_ZF[base + 4]) = make_float4(zf[4], zf[5], zf[6], zf[7]);
        s_ssq[r][tx] = ssq;
        s_sxz[r][tx] = sxz;
    }
    __syncthreads();
    if (tid < 128) {
        float ssq = 0.f, sxz = 0.f;
        #pragma unroll
        for (int t = 0; t < 16; t++) { ssq += s_ssq[tid][t]; sxz += s_sxz[tid][t]; }
        g_dist[row0 + tid] = ssq - 2.f * sxz;   // xn dropped (argmin-invariant)
    }
}

// ---------------- select: argmin over 256 candidates, update xhat, emit outputs ----------------
__global__ void k_select(float* __restrict__ out, int m) {
    __shared__ float s_v[256];
    __shared__ int   s_i[256];
    int b = blockIdx.x, t = threadIdx.x;
    s_v[t] = g_dist[b * Kq + t];
    s_i[t] = t;
    __syncthreads();
    for (int s = 128; s > 0; s >>= 1) {
        if (t < s) {
            float v2 = s_v[t + s]; int i2 = s_i[t + s];
            if (v2 < s_v[t] || (v2 == s_v[t] && i2 < s_i[t])) { s_v[t] = v2; s_i[t] = i2; }
        }
        __syncthreads();
    }
    int idx = s_i[0];
    if (t < Dq) {
        float v = g_ZF[(b * Kq + idx) * Dq + t];
        g_xhat[b * Dq + t] = v;
        out[OUT_SIDE + (m + 1) * (BSq * Dq) + b * Dq + t] = v;  // side[m+1]
        if (m == Mq - 2) out[b * Dq + t] = v;                   // final xhat
    }
    if (t == 0) out[OUT_CODES + b * Mq + m + 1] = (float)idx;
}

// ---------------- launch ----------------
extern "C" void kernel_launch(void* const* d_in, const int* in_sizes, int n_in,
                              void* d_out, int out_size) {
    const float* x   = (const float*)d_in[0];   // [1024,128]
    const float* cb0 = (const float*)d_in[1];   // [256,128]
    const float* cbs = (const float*)d_in[2];   // [7,256,128]
    const float* Wc  = (const float*)d_in[3];   // [7,128,256]
    const float* bc  = (const float*)d_in[4];   // [7,128]
    const float* W1  = (const float*)d_in[5];   // [7,2,256,128]
    const float* W2  = (const float*)d_in[6];   // [7,2,128,256]
    float* out = (float*)d_out;

    k_code0<<<BSq, 256>>>(x, cb0, out);

    for (int m = 0; m < Mq - 1; m++) {
        const float* cb  = cbs + m * Kq * Dq;
        const float* Wcm = Wc  + m * Dq * (2 * Dq);
        const float* bcm = bc  + m * Dq;
        const float* W10 = W1  + (m * 2 + 0) * Hq * Dq;
        const float* W11 = W1  + (m * 2 + 1) * Hq * Dq;
        const float* W20 = W2  + (m * 2 + 0) * Dq * Hq;
        const float* W21 = W2  + (m * 2 + 1) * Dq * Hq;

        k_ck<<<Kq, 128>>>(cb, Wcm);
        k_a0<<<Kq, 256>>>(W10);
        k_xb<<<BSq, 128>>>(Wcm, bcm);
        k_b0<<<BSq, 256>>>(W10);
        gemmA<<<2048, 256>>>(W20);
        gemmB<<<4096, 256>>>(W11);
        gemmC<<<2048, 256>>>(x, W21);
        k_select<<<BSq, 256>>>(out, m);
    }
}

// round 9
// speedup vs baseline: 1.1087x; 1.1087x over previous
#include <cuda_runtime.h>
#include <cstdint>

// QINCo: D=128, M=8, K=256, L=2, H=256, BS=1024
#define Dq   128
#define Mq   8
#define Kq   256
#define Hq   256
#define BSq  1024
#define NROW (BSq * Kq)          // 262144 candidate rows per step

// Output layout (float32): xhat[BS*D], codes[BS*M] (as float), side[0..7][BS*D]
#define OUT_CODES (BSq * Dq)                 // 131072
#define OUT_SIDE  (OUT_CODES + BSq * Mq)     // 139264

// ---------------- device scratch (static, no allocs) ----------------
__device__ float g_xhat[BSq * Dq];
__device__ float g_Ck[Kq * Dq];              // cb + cb@Wz^T
__device__ float g_A0[Kq * Hq];              // Ck@W1_0^T
__device__ float g_Xb[BSq * Dq];             // xhat@Wx^T + bc
__device__ float g_B0[BSq * Hq];             // Xb@W1_0^T
__device__ float g_Z1[NROW * Dq];            // 134 MB
__device__ float g_H1[NROW * Hq];            // 268 MB
__device__ float g_ZF[NROW * Dq];            // 134 MB
__device__ float g_dist[NROW];

// ---------------- packed f32x2 helpers (Blackwell base ISA, no 'a' needed) ----------------
__device__ __forceinline__ void ffma2(unsigned long long& d, unsigned long long a, unsigned long long b) {
    asm("fma.rn.f32x2 %0, %1, %2, %0;" : "+l"(d) : "l"(a), "l"(b));
}
__device__ __forceinline__ unsigned long long bcast2(float v) {
    unsigned long long r;
    asm("mov.b64 %0, {%1, %1};" : "=l"(r) : "f"(v));
    return r;
}
__device__ __forceinline__ float2 unpk2(unsigned long long v) {
    float lo, hi;
    asm("mov.b64 {%0, %1}, %2;" : "=f"(lo), "=f"(hi) : "l"(v));
    return make_float2(lo, hi);
}

// ---------------- step 0: code0 = argmin ||x - cb0_k||^2 ----------------
__global__ void k_code0(const float* __restrict__ x,
                        const float* __restrict__ cb0,
                        float* __restrict__ out) {
    __shared__ float s_x[Dq];
    __shared__ float s_v[256];
    __shared__ int   s_i[256];
    int b = blockIdx.x, t = threadIdx.x;
    if (t < Dq) s_x[t] = x[b * Dq + t];
    __syncthreads();
    const float* c = cb0 + t * Dq;
    float acc1 = 0.f, acc2 = 0.f;
    #pragma unroll 8
    for (int d = 0; d < Dq; d++) {
        float cv = c[d];
        acc1 = fmaf(cv, cv, acc1);
        acc2 = fmaf(s_x[d], cv, acc2);
    }
    s_v[t] = acc1 - 2.f * acc2;
    s_i[t] = t;
    __syncthreads();
    for (int s = 128; s > 0; s >>= 1) {
        if (t < s) {
            float v2 = s_v[t + s]; int i2 = s_i[t + s];
            if (v2 < s_v[t] || (v2 == s_v[t] && i2 < s_i[t])) { s_v[t] = v2; s_i[t] = i2; }
        }
        __syncthreads();
    }
    int idx = s_i[0];
    if (t < Dq) {
        float v = cb0[idx * Dq + t];
        g_xhat[b * Dq + t] = v;
        out[OUT_SIDE + b * Dq + t] = v;   // side[0]
    }
    if (t == 0) out[OUT_CODES + b * Mq + 0] = (float)idx;
}

// ---------------- per-step small prep kernels ----------------
__global__ void k_ck(const float* __restrict__ cb, const float* __restrict__ Wcm) {
    __shared__ float s[Dq];
    int k = blockIdx.x, t = threadIdx.x;
    s[t] = cb[k * Dq + t];
    __syncthreads();
    float acc = s[t];
    const float* w = Wcm + t * (2 * Dq);
    #pragma unroll 8
    for (int d = 0; d < Dq; d++) acc = fmaf(s[d], w[d], acc);
    g_Ck[k * Dq + t] = acc;
}
__global__ void k_a0(const float* __restrict__ W10) {
    __shared__ float s[Dq];
    int k = blockIdx.x, t = threadIdx.x;
    if (t < Dq) s[t] = g_Ck[k * Dq + t];
    __syncthreads();
    float acc = 0.f;
    const float* w = W10 + t * Dq;
    #pragma unroll 8
    for (int d = 0; d < Dq; d++) acc = fmaf(s[d], w[d], acc);
    g_A0[k * Hq + t] = acc;
}
__global__ void k_xb(const float* __restrict__ Wcm, const float* __restrict__ bcm) {
    __shared__ float s[Dq];
    int b = blockIdx.x, t = threadIdx.x;
    s[t] = g_xhat[b * Dq + t];
    __syncthreads();
    float acc = bcm[t];
    const float* w = Wcm + t * (2 * Dq) + Dq;
    #pragma unroll 8
    for (int d = 0; d < Dq; d++) acc = fmaf(s[d], w[d], acc);
    g_Xb[b * Dq + t] = acc;
}
__global__ void k_b0(const float* __restrict__ W10) {
    __shared__ float s[Dq];
    int b = blockIdx.x, t = threadIdx.x;
    if (t < Dq) s[t] = g_Xb[b * Dq + t];
    __syncthreads();
    float acc = 0.f;
    const float* w = W10 + t * Dq;
    #pragma unroll 8
    for (int d = 0; d < Dq; d++) acc = fmaf(s[d], w[d], acc);
    g_B0[b * Hq + t] = acc;
}

// ================= FFMA2 inner-product core =================
// acc[i][jp] is a packed f32x2 pair covering output cols (tx*8+2jp, tx*8+2jp+1).
#define INNER_STEP(Rsrc, Wsrc)                                                  \
    do {                                                                        \
        float4 a0 = *(const float4*)(&Rsrc[h][ty * 8]);                         \
        float4 a1 = *(const float4*)(&Rsrc[h][ty * 8 + 4]);                     \
        ulonglong2 wv0 = *(const ulonglong2*)(&Wsrc[h][tx * 8]);                \
        ulonglong2 wv1 = *(const ulonglong2*)(&Wsrc[h][tx * 8 + 4]);            \
        unsigned long long ap[8] = {bcast2(a0.x), bcast2(a0.y), bcast2(a0.z),   \
                                    bcast2(a0.w), bcast2(a1.x), bcast2(a1.y),   \
                                    bcast2(a1.z), bcast2(a1.w)};                \
        unsigned long long wp[4] = {wv0.x, wv0.y, wv1.x, wv1.y};                \
        _Pragma("unroll")                                                       \
        for (int i = 0; i < 8; i++) {                                           \
            ffma2(acc[i][0], ap[i], wp[0]);                                     \
            ffma2(acc[i][1], ap[i], wp[1]);                                     \
            ffma2(acc[i][2], ap[i], wp[2]);                                     \
            ffma2(acc[i][3], ap[i], wp[3]);                                     \
        }                                                                       \
    } while (0)

// ---------------- GEMM A: Z1 = Ck+Xb + relu(A0+B0) @ W2_0^T ----------------
__global__ __launch_bounds__(256) void gemmA(const float* __restrict__ W20) {
    __shared__ __align__(16) float Rs[16][132];
    __shared__ __align__(16) float Ws[16][132];
    int bx = blockIdx.x;              // 0..2047
    int b  = bx >> 1;
    int k0 = (bx & 1) * 128;
    int row0 = b * Kq + k0;
    int tid = threadIdx.x;
    int tx = tid & 15, ty = tid >> 4;
    unsigned long long acc[8][4] = {};
    const float* A0p = g_A0 + k0 * Hq;
    const float* B0p = g_B0 + b * Hq;
    for (int kk = 0; kk < Hq; kk += 16) {
        #pragma unroll
        for (int it = 0; it < 8; it++) {
            int idx = tid + it * 256;
            int r = idx >> 4, h = idx & 15;
            float v = A0p[r * Hq + kk + h] + B0p[kk + h];
            Rs[h][r] = fmaxf(v, 0.f);
        }
        #pragma unroll
        for (int it = 0; it < 8; it++) {
            int idx = tid + it * 256;
            int d = idx >> 4, h = idx & 15;
            Ws[h][d] = W20[d * Hq + kk + h];
        }
        __syncthreads();
        #pragma unroll
        for (int h = 0; h < 16; h++) INNER_STEP(Rs, Ws);
        __syncthreads();
    }
    const float* Ckp = g_Ck + k0 * Dq;
    const float* Xbp = g_Xb + b * Dq;
    #pragma unroll
    for (int i = 0; i < 8; i++) {
        int r = ty * 8 + i;
        int base = (row0 + r) * Dq + tx * 8;
        const float* ck = Ckp + r * Dq + tx * 8;
        const float* xb = Xbp + tx * 8;
        float2 p0 = unpk2(acc[i][0]), p1 = unpk2(acc[i][1]);
        float2 p2 = unpk2(acc[i][2]), p3 = unpk2(acc[i][3]);
        float4 o0 = make_float4(p0.x + ck[0] + xb[0], p0.y + ck[1] + xb[1],
                                p1.x + ck[2] + xb[2], p1.y + ck[3] + xb[3]);
        float4 o1 = make_float4(p2.x + ck[4] + xb[4], p2.y + ck[5] + xb[5],
                                p3.x + ck[6] + xb[6], p3.y + ck[7] + xb[7]);
        *(float4*)(&g_Z1[base])     = o0;
        *(float4*)(&g_Z1[base + 4]) = o1;
    }
}

// ---------------- GEMM B: H1 = relu(Z1 @ W1_1^T) ----------------
__global__ __launch_bounds__(256) void gemmB(const float* __restrict__ W11) {
    __shared__ __align__(16) float Zs[16][132];
    __shared__ __align__(16) float W1s[16][132];
    int bx = blockIdx.x;
    int row0 = (bx >> 1) * 128;
    int h0   = (bx & 1) * 128;
    int tid = threadIdx.x;
    int tx = tid & 15, ty = tid >> 4;
    unsigned long long acc[8][4] = {};
    for (int dd = 0; dd < Dq; dd += 16) {
        #pragma unroll
        for (int it = 0; it < 8; it++) {
            int idx = tid + it * 256;
            int r = idx >> 4, d = idx & 15;
            Zs[d][r] = g_Z1[(row0 + r) * Dq + dd + d];
        }
        #pragma unroll
        for (int it = 0; it < 8; it++) {
            int idx = tid + it * 256;
            int c = idx >> 4, d = idx & 15;
            W1s[d][c] = W11[(h0 + c) * Dq + dd + d];
        }
        __syncthreads();
        #pragma unroll
        for (int h = 0; h < 16; h++) INNER_STEP(Zs, W1s);
        __syncthreads();
    }
    #pragma unroll
    for (int i = 0; i < 8; i++) {
        int r = ty * 8 + i;
        int base = (row0 + r) * Hq + h0 + tx * 8;
        float2 p0 = unpk2(acc[i][0]), p1 = unpk2(acc[i][1]);
        float2 p2 = unpk2(acc[i][2]), p3 = unpk2(acc[i][3]);
        float4 o0 = make_float4(fmaxf(p0.x, 0.f), fmaxf(p0.y, 0.f),
                                fmaxf(p1.x, 0.f), fmaxf(p1.y, 0.f));
        float4 o1 = make_float4(fmaxf(p2.x, 0.f), fmaxf(p2.y, 0.f),
                                fmaxf(p3.x, 0.f), fmaxf(p3.y, 0.f));
        *(float4*)(&g_H1[base])     = o0;
        *(float4*)(&g_H1[base + 4]) = o1;
    }
}

// ---------------- GEMM C: ZF = Z1 + H1 @ W2_1^T + xhat; dist epilogue ----------------
__global__ __launch_bounds__(256) void gemmC(const float* __restrict__ x,
                                             const float* __restrict__ W21) {
    __shared__ __align__(16) float Hs[16][132];
    __shared__ __align__(16) float Ws[16][132];
    __shared__ float s_ssq[128][17];
    __shared__ float s_sxz[128][17];
    __shared__ float s_x[Dq];
    __shared__ float s_xh[Dq];
    int bx = blockIdx.x;              // 0..2047
    int row0 = bx * 128;
    int b = bx >> 1;
    int tid = threadIdx.x;
    int tx = tid & 15, ty = tid >> 4;
    if (tid < Dq) { s_x[tid] = x[b * Dq + tid]; s_xh[tid] = g_xhat[b * Dq + tid]; }
    unsigned long long acc[8][4] = {};
    for (int kk = 0; kk < Hq; kk += 16) {
        #pragma unroll
        for (int it = 0; it < 8; it++) {
            int idx = tid + it * 256;
            int r = idx >> 4, h = idx & 15;
            Hs[h][r] = g_H1[(row0 + r) * Hq + kk + h];
        }
        #pragma unroll
        for (int it = 0; it < 8; it++) {
            int idx = tid + it * 256;
            int d = idx >> 4, h = idx & 15;
            Ws[h][d] = W21[d * Hq + kk + h];
        }
        __syncthreads();
        #pragma unroll
        for (int h = 0; h < 16; h++) INNER_STEP(Hs, Ws);
        __syncthreads();
    }
    #pragma unroll
    for (int i = 0; i < 8; i++) {
        int r = ty * 8 + i;
        int base = (row0 + r) * Dq + tx * 8;
        float ssq = 0.f, sxz = 0.f;
        float zf[8];
        float2 p[4] = {unpk2(acc[i][0]), unpk2(acc[i][1]), unpk2(acc[i][2]), unpk2(acc[i][3])};
        #pragma unroll
        for (int jp = 0; jp < 4; jp++) {
            int j0 = jp * 2;
            float v0 = p[jp].x + g_Z1[base + j0]     + s_xh[tx * 8 + j0];
            float v1 = p[jp].y + g_Z1[base + j0 + 1] + s_xh[tx * 8 + j0 + 1];
            zf[j0] = v0; zf[j0 + 1] = v1;
            ssq = fmaf(v0, v0, fmaf(v1, v1, ssq));
            sxz = fmaf(s_x[tx * 8 + j0], v0, fmaf(s_x[tx * 8 + j0 + 1], v1, sxz));
        }
        *(float4*)(&g_ZF[base])     = make_float4(zf[0], zf[1], zf[2], zf[3]);
        *(float4*)(&g_ZF[base + 4]) = make_float4(zf[4], zf[5], zf[6], zf[7]);
        s_ssq[r][tx] = ssq;
        s_sxz[r][tx] = sxz;
    }
    __syncthreads();
    if (tid < 128) {
        float ssq = 0.f, sxz = 0.f;
        #pragma unroll
        for (int t = 0; t < 16; t++) { ssq += s_ssq[tid][t]; sxz += s_sxz[tid][t]; }
        g_dist[row0 + tid] = ssq - 2.f * sxz;
    }
}

// ---------------- select ----------------
__global__ void k_select(float* __restrict__ out, int m) {
    __shared__ float s_v[256];
    __shared__ int   s_i[256];
    int b = blockIdx.x, t = threadIdx.x;
    s_v[t] = g_dist[b * Kq + t];
    s_i[t] = t;
    __syncthreads();
    for (int s = 128; s > 0; s >>= 1) {
        if (t < s) {
            float v2 = s_v[t + s]; int i2 = s_i[t + s];
            if (v2 < s_v[t] || (v2 == s_v[t] && i2 < s_i[t])) { s_v[t] = v2; s_i[t] = i2; }
        }
        __syncthreads();
    }
    int idx = s_i[0];
    if (t < Dq) {
        float v = g_ZF[(b * Kq + idx) * Dq + t];
        g_xhat[b * Dq + t] = v;
        out[OUT_SIDE + (m + 1) * (BSq * Dq) + b * Dq + t] = v;
        if (m == Mq - 2) out[b * Dq + t] = v;
    }
    if (t == 0) out[OUT_CODES + b * Mq + m + 1] = (float)idx;
}

// ---------------- launch ----------------
extern "C" void kernel_launch(void* const* d_in, const int* in_sizes, int n_in,
                              void* d_out, int out_size) {
    const float* x   = (const float*)d_in[0];   // [1024,128]
    const float* cb0 = (const float*)d_in[1];   // [256,128]
    const float* cbs = (const float*)d_in[2];   // [7,256,128]
    const float* Wc  = (const float*)d_in[3];   // [7,128,256]
    const float* bc  = (const float*)d_in[4];   // [7,128]
    const float* W1  = (const float*)d_in[5];   // [7,2,256,128]
    const float* W2  = (const float*)d_in[6];   // [7,2,128,256]
    float* out = (float*)d_out;

    k_code0<<<BSq, 256>>>(x, cb0, out);

    for (int m = 0; m < Mq - 1; m++) {
        const float* cb  = cbs + m * Kq * Dq;
        const float* Wcm = Wc  + m * Dq * (2 * Dq);
        const float* bcm = bc  + m * Dq;
        const float* W10 = W1  + (m * 2 + 0) * Hq * Dq;
        const float* W11 = W1  + (m * 2 + 1) * Hq * Dq;
        const float* W20 = W2  + (m * 2 + 0) * Dq * Hq;
        const float* W21 = W2  + (m * 2 + 1) * Dq * Hq;

        k_ck<<<Kq, 128>>>(cb, Wcm);
        k_a0<<<Kq, 256>>>(W10);
        k_xb<<<BSq, 128>>>(Wcm, bcm);
        k_b0<<<BSq, 256>>>(W10);
        gemmA<<<2048, 256>>>(W20);
        gemmB<<<4096, 256>>>(W11);
        gemmC<<<2048, 256>>>(x, W21);
        k_select<<<BSq, 256>>>(out, m);
    }
}